// round 11
// baseline (speedup 1.0000x reference)
#include <cuda_runtime.h>
#include <cuda_fp16.h>
#include <cstdint>

// ============================================================================
// SparseSubdivideBlock3d via legacy HMMA (mma.sync fp16) — one-sided split.
// R10: numerics changed from bf16x3 (3 MMAs/product) to fp16x2 (2 MMAs):
//   A kept as single fp16 (features/h); B (weights) split hi+lo fp16:
//     out ~= A*Bhi + A*Blo ; error = (x - fp16(x))*y ~ 2^-11 rms per layer.
// Pipeline/tiling identical to R9 (64x128 tile, K-chunk 64, 2-stage mbarrier
// producer/consumer, 2 CTAs/SM).
//
// Algorithm (validated R4 @ fp32):
//   conv1: 27-tap submanifold conv, C=128->128, +bias, SiLU
//   subdivide collapse: conv2 == 8-tap conv on the COARSE grid with
//     pre-combined weights Wc[p][e] = sum W2[k], out row = 8*v + p.
// ============================================================================

#define N_VOX 40000
#define C 128

// ---- device scratch ----
__device__ __align__(16) __half g_w1t_hi[27 * C * C];      // W1^T [k][co][ci]
__device__ __align__(16) __half g_w1t_lo[27 * C * C];
__device__ __align__(16) __half g_wct_hi[64 * C * C];      // Wc^T [pe][co][ci]
__device__ __align__(16) __half g_wct_lo[64 * C * C];
__device__ __align__(16) __half g_f[(N_VOX + 1) * C];      // feats fp16 + zero pad row
__device__ __align__(16) __half g_h[(N_VOX + 1) * C];      // layer-1 out fp16 + pad

__device__ __forceinline__ float silu_f(float x) { return x / (1.0f + __expf(-x)); }

__device__ __forceinline__ uint32_t smem_u32(const void* p) {
    uint32_t a;
    asm("{ .reg .u64 t; cvta.to.shared.u64 t, %1; cvt.u32.u64 %0, t; }" : "=r"(a) : "l"(p));
    return a;
}
#define CP16(dst, src) asm volatile("cp.async.cg.shared.global [%0], [%1], 16;" :: "r"(dst), "l"(src))
#define CPA_ARRIVE(mb)  asm volatile("cp.async.mbarrier.arrive.noinc.shared.b64 [%0];" :: "r"((uint32_t)(mb)) : "memory")
#define MBAR_INIT(mb, n) asm volatile("mbarrier.init.shared.b64 [%0], %1;" :: "r"((uint32_t)(mb)), "r"((uint32_t)(n)) : "memory")
#define MBAR_ARRIVE(mb)  asm volatile("mbarrier.arrive.shared.b64 _, [%0];" :: "r"((uint32_t)(mb)) : "memory")

#define MBAR_WAIT(mb, ph) do {                                                             \
    uint32_t _m = (uint32_t)(mb), _p = (uint32_t)(ph), _d;                                 \
    asm volatile("{\n\t.reg .pred p;\n\t"                                                  \
        "mbarrier.try_wait.parity.acquire.cta.shared::cta.b64 p, [%1], %2;\n\t"            \
        "selp.b32 %0, 1, 0, p;\n\t}" : "=r"(_d) : "r"(_m), "r"(_p) : "memory");            \
    if (!_d) {                                                                             \
        asm volatile("{\n\t.reg .pred P1;\n\t"                                             \
            "WL_%=:\n\t"                                                                   \
            "mbarrier.try_wait.parity.acquire.cta.shared::cta.b64 P1, [%0], %1, 0x989680;\n\t" \
            "@P1 bra.uni WD_%=;\n\t"                                                       \
            "bra.uni WL_%=;\n\t"                                                           \
            "WD_%=:\n\t}" :: "r"(_m), "r"(_p) : "memory");                                 \
    }                                                                                      \
} while (0)

__device__ __forceinline__ void ldsm_x4(uint32_t* r, uint32_t a) {
    asm volatile("ldmatrix.sync.aligned.m8n8.x4.shared.b16 {%0,%1,%2,%3}, [%4];"
                 : "=r"(r[0]), "=r"(r[1]), "=r"(r[2]), "=r"(r[3]) : "r"(a));
}
__device__ __forceinline__ void mma16816(float* d, const uint32_t* a, const uint32_t* b) {
    asm volatile("mma.sync.aligned.m16n8k16.row.col.f32.f16.f16.f32 "
                 "{%0,%1,%2,%3}, {%4,%5,%6,%7}, {%8,%9}, {%0,%1,%2,%3};"
                 : "+f"(d[0]), "+f"(d[1]), "+f"(d[2]), "+f"(d[3])
                 : "r"(a[0]), "r"(a[1]), "r"(a[2]), "r"(a[3]), "r"(b[0]), "r"(b[1]));
}

__device__ __forceinline__ void split_h16(float x, __half& hi, __half& lo) {
    hi = __float2half(x);
    lo = __float2half(x - __half2float(hi));
}

// ---------------------------------------------------------------------------
// Prep: fused build + split + transpose.
// ---------------------------------------------------------------------------
__global__ void build_wct_kernel(const float* __restrict__ W2) {
    __shared__ float s[32][33];
    const int pe = blockIdx.y;
    const int p = pe >> 3, e = pe & 7;
    const int pp[3] = { (p >> 2) & 1, (p >> 1) & 1, p & 1 };
    const int ee[3] = { (e >> 2) & 1, (e >> 1) & 1, e & 1 };
    int offs[3][2], cnt[3];
    #pragma unroll
    for (int d = 0; d < 3; d++) {
        if (ee[d] == pp[d]) { cnt[d] = 1; offs[d][0] = pp[d] ? 1 : -1; offs[d][1] = 0; }
        else if (pp[d] == 0) { cnt[d] = 2; offs[d][0] = 0;  offs[d][1] = 1; }
        else                 { cnt[d] = 2; offs[d][0] = -1; offs[d][1] = 0; }
    }
    const int ci0 = (blockIdx.x >> 2) * 32, co0 = (blockIdx.x & 3) * 32;
    const int tx = threadIdx.x;
    const int r = tx >> 3, c4 = (tx & 7) * 4;

    float4 sum = make_float4(0.f, 0.f, 0.f, 0.f);
    for (int a = 0; a < cnt[0]; a++)
        for (int b = 0; b < cnt[1]; b++)
            for (int c = 0; c < cnt[2]; c++) {
                int k = (offs[0][a] + 1) * 9 + (offs[1][b] + 1) * 3 + (offs[2][c] + 1);
                float4 v = *(const float4*)(W2 + (size_t)k * (C * C) + (size_t)(ci0 + r) * C + co0 + c4);
                sum.x += v.x; sum.y += v.y; sum.z += v.z; sum.w += v.w;
            }
    s[r][c4] = sum.x; s[r][c4 + 1] = sum.y; s[r][c4 + 2] = sum.z; s[r][c4 + 3] = sum.w;
    __syncthreads();

    __half hi[4], lo[4];
    #pragma unroll
    for (int j = 0; j < 4; ++j) split_h16(s[c4 + j][r], hi[j], lo[j]);
    const size_t o = (size_t)pe * (C * C) + (size_t)(co0 + r) * C + ci0 + c4;
    *(uint2*)(g_wct_hi + o) = *(const uint2*)hi;
    *(uint2*)(g_wct_lo + o) = *(const uint2*)lo;
}

__global__ void build_w1t_kernel(const float* __restrict__ W1) {
    __shared__ float s[32][33];
    const int k = blockIdx.y;
    const int ci0 = (blockIdx.x >> 2) * 32, co0 = (blockIdx.x & 3) * 32;
    const int tx = threadIdx.x;
    const int r = tx >> 3, c4 = (tx & 7) * 4;
    float4 v = *(const float4*)(W1 + (size_t)k * (C * C) + (size_t)(ci0 + r) * C + co0 + c4);
    s[r][c4] = v.x; s[r][c4 + 1] = v.y; s[r][c4 + 2] = v.z; s[r][c4 + 3] = v.w;
    __syncthreads();
    __half hi[4], lo[4];
    #pragma unroll
    for (int j = 0; j < 4; ++j) split_h16(s[c4 + j][r], hi[j], lo[j]);
    const size_t o = (size_t)k * (C * C) + (size_t)(co0 + r) * C + ci0 + c4;
    *(uint2*)(g_w1t_hi + o) = *(const uint2*)hi;
    *(uint2*)(g_w1t_lo + o) = *(const uint2*)lo;
}

// feats -> fp16 (single); zero pad rows of f and h
__global__ void split_feats_kernel(const float* __restrict__ f) {
    const size_t i4 = ((size_t)blockIdx.x * blockDim.x + threadIdx.x) * 4;
    const size_t tot = (size_t)(N_VOX + 1) * C;
    if (i4 >= tot) return;
    float4 v;
    const bool pad = i4 >= (size_t)N_VOX * C;
    if (pad) v = make_float4(0.f, 0.f, 0.f, 0.f);
    else     v = *(const float4*)(f + i4);
    __half h[4];
    h[0] = __float2half(v.x); h[1] = __float2half(v.y);
    h[2] = __float2half(v.z); h[3] = __float2half(v.w);
    *(uint2*)(g_f + i4) = *(const uint2*)h;
    if (pad) *(uint2*)(g_h + i4) = *(const uint2*)h;   // zeros
}

// ---------------------------------------------------------------------------
// Main conv kernel: 256 threads, block = 64 voxels x 128 outputs, 2 CTAs/SM.
// SMEM: [0,512) bias | [512,7424) sIdx | [7424,7456) mbarriers
//       [8192, +2*40960) stage bufs (A 8K | B hi 16K | B lo 16K)
// K chunk = 64, 2-stage mbarrier full/empty pipeline (as R9).
// Swizzle: 16B chunk col c at row r stored at chunk (c ^ (r&7)); row = 128B.
// ---------------------------------------------------------------------------
#define MBAR_BASE 7424
#define BUF_OFF 8192
#define STAGE   40960
#define SMEM_TOTAL (BUF_OFF + 2 * STAGE)

template <int NOFF, bool L2>
__global__ __launch_bounds__(256, 2)
void conv_mma(const __half* __restrict__ fin,
              const __half* __restrict__ whi, const __half* __restrict__ wlo,
              const int* __restrict__ nbr, const float* __restrict__ bias,
              float* __restrict__ out, __half* __restrict__ oh) {
    extern __shared__ __align__(1024) char smem[];
    const uint32_t sb = smem_u32(smem);
    const int tx = threadIdx.x, wid = tx >> 5, lane = tx & 31;
    const int m0 = blockIdx.x * 64;
    const int p  = L2 ? blockIdx.y : 0;
    const int p0 = (p >> 2) & 1, p1 = (p >> 1) & 1, p2 = p & 1;
    const int wm = wid & 1;            // 0..1 : 32-row slab
    const int wn = wid >> 1;           // 0..3 : 32-col slab

    float* sBias = (float*)smem;
    int*   sIdx  = (int*)(smem + 512);
    const uint32_t mbFull0  = sb + MBAR_BASE + 0;
    const uint32_t mbFull1  = sb + MBAR_BASE + 8;
    const uint32_t mbEmpty0 = sb + MBAR_BASE + 16;
    const uint32_t mbEmpty1 = sb + MBAR_BASE + 24;

    if (tx == 0) {
        MBAR_INIT(mbFull0, 256);  MBAR_INIT(mbFull1, 256);
        MBAR_INIT(mbEmpty0, 256); MBAR_INIT(mbEmpty1, 256);
    }
    if (tx < C) sBias[tx] = bias[tx];
    for (int t = tx; t < NOFF * 64; t += 256) {
        const int tap = t >> 6, r = t & 63;
        const int col = L2 ? ((((tap >> 2) & 1) + p0) * 9 + (((tap >> 1) & 1) + p1) * 3 + ((tap & 1) + p2))
                           : tap;
        sIdx[t] = nbr[(size_t)(m0 + r) * 27 + col];   // 625*64 == N_VOX exactly
    }
    __syncthreads();   // mbarrier init + sIdx visible

    const int NCHUNK = NOFF * 2;

    auto load_chunk = [&](int ch, int buf) {
        const int tap = ch >> 1;
        const int kb  = (ch & 1) * 64;
        const uint32_t base = sb + BUF_OFF + (uint32_t)buf * STAGE;
        const int slice = L2 ? (p * 8 + tap) : tap;
        const __half* wsl_h = whi + (size_t)slice * (C * C);
        const __half* wsl_l = wlo + (size_t)slice * (C * C);
        const int* idx = sIdx + tap * 64;
        #pragma unroll
        for (int i = 0; i < 2; ++i) {                  // A: 512 16B chunks (fp16 single)
            const int op = tx + i * 256;
            const int row = op >> 3, c = op & 7;
            const int g = idx[row];
            const __half* src = fin + (size_t)g * C + kb + c * 8;
            const uint32_t dst = base + (uint32_t)(row * 128 + ((c ^ (row & 7)) << 4));
            CP16(dst, src);
        }
        #pragma unroll
        for (int i = 0; i < 8; ++i) {                  // B hi+lo: 2048 chunks
            const int op = tx + i * 256;
            const int part = op >> 10;
            const int rc = op & 1023, row = rc >> 3, c = rc & 7;
            const __half* src = (part ? wsl_l : wsl_h) + (size_t)row * C + kb + c * 8;
            const uint32_t dst = base + 8192u + (uint32_t)part * 16384u
                               + (uint32_t)(row * 128 + ((c ^ (row & 7)) << 4));
            CP16(dst, src);
        }
    };

    float acc[2][4][4];
    #pragma unroll
    for (int i = 0; i < 2; i++)
        #pragma unroll
        for (int j = 0; j < 4; j++)
            #pragma unroll
            for (int q = 0; q < 4; q++) acc[i][j][q] = 0.0f;

    // prologue: fill both stages
    load_chunk(0, 0); CPA_ARRIVE(mbFull0);
    load_chunk(1, 1); CPA_ARRIVE(mbFull1);

    #pragma unroll 1
    for (int ch = 0; ch < NCHUNK; ++ch) {
        const int b  = ch & 1;
        const int ph = (ch >> 1) & 1;
        const uint32_t mbF = b ? mbFull1 : mbFull0;
        const uint32_t mbE = b ? mbEmpty1 : mbEmpty0;

        MBAR_WAIT(mbF, ph);                    // loads for chunk ch complete

        const uint32_t base = sb + BUF_OFF + (uint32_t)b * STAGE;
        const uint32_t aB = base, bHi = base + 8192u, bLo = base + 24576u;

        #pragma unroll
        for (int k16 = 0; k16 < 4; ++k16) {
            uint32_t ah[2][4], bh[4][2], bl[4][2];
            #pragma unroll
            for (int i = 0; i < 2; ++i) {
                const int row = wm * 32 + 16 * i + (lane & 15);
                const int c = (k16 << 1) + (lane >> 4);
                const uint32_t off = (uint32_t)(row * 128 + ((c ^ (row & 7)) << 4));
                ldsm_x4(ah[i], aB + off);
            }
            #pragma unroll
            for (int jj = 0; jj < 2; ++jj) {
                const int grp = lane >> 3;
                const int row = wn * 32 + 16 * jj + ((grp >> 1) << 3) + (lane & 7);
                const int c = (k16 << 1) + (grp & 1);
                const uint32_t off = (uint32_t)(row * 128 + ((c ^ (row & 7)) << 4));
                uint32_t t[4];
                ldsm_x4(t, bHi + off);
                bh[jj * 2][0] = t[0]; bh[jj * 2][1] = t[1];
                bh[jj * 2 + 1][0] = t[2]; bh[jj * 2 + 1][1] = t[3];
                ldsm_x4(t, bLo + off);
                bl[jj * 2][0] = t[0]; bl[jj * 2][1] = t[1];
                bl[jj * 2 + 1][0] = t[2]; bl[jj * 2 + 1][1] = t[3];
            }
            #pragma unroll
            for (int i = 0; i < 2; ++i)
                #pragma unroll
                for (int j = 0; j < 4; ++j) {
                    mma16816(acc[i][j], ah[i], bh[j]);
                    mma16816(acc[i][j], ah[i], bl[j]);
                }
        }

        MBAR_ARRIVE(mbE);                      // done reading buffer b
        if (ch + 2 < NCHUNK) {
            MBAR_WAIT(mbE, ph);                // buffer reusable by all threads
            load_chunk(ch + 2, b);
            CPA_ARRIVE(mbF);
        }
    }

    // ---- epilogue: bias + SiLU ----
    const int lrow = lane >> 2;             // 0..7
    const int lcol = (lane & 3) * 2;        // 0,2,4,6
    #pragma unroll
    for (int i = 0; i < 2; ++i) {
        const int r0 = m0 + wm * 32 + 16 * i + lrow;
        const int r1 = r0 + 8;
        #pragma unroll
        for (int j = 0; j < 4; ++j) {
            const int cb = wn * 32 + 8 * j + lcol;
            const float b0 = sBias[cb], b1 = sBias[cb + 1];
            float v00 = silu_f(acc[i][j][0] + b0), v01 = silu_f(acc[i][j][1] + b1);
            float v10 = silu_f(acc[i][j][2] + b0), v11 = silu_f(acc[i][j][3] + b1);
            if (L2) {
                *(float2*)(out + ((size_t)r0 * 8 + p) * C + cb) = make_float2(v00, v01);
                *(float2*)(out + ((size_t)r1 * 8 + p) * C + cb) = make_float2(v10, v11);
            } else {
                __half h[2];
                h[0] = __float2half(v00); h[1] = __float2half(v01);
                *(uint32_t*)(oh + (size_t)r0 * C + cb) = *(const uint32_t*)h;
                h[0] = __float2half(v10); h[1] = __float2half(v11);
                *(uint32_t*)(oh + (size_t)r1 * C + cb) = *(const uint32_t*)h;
            }
        }
    }
}

// ---------------------------------------------------------------------------
// Inputs (metadata order): feats, W1, b1, W2, b2, nbr1, nbr2(unused)
// Output: 320000 x 128 fp32
// ---------------------------------------------------------------------------
extern "C" void kernel_launch(void* const* d_in, const int* in_sizes, int n_in,
                              void* d_out, int out_size) {
    const float* feats = (const float*)d_in[0];
    const float* W1    = (const float*)d_in[1];
    const float* b1    = (const float*)d_in[2];
    const float* W2    = (const float*)d_in[3];
    const float* b2    = (const float*)d_in[4];
    const int*   nbr1  = (const int*)  d_in[5];
    float*       out   = (float*)d_out;

    __half *f16, *h16, *w1h, *w1l, *wch, *wcl;
    cudaGetSymbolAddress((void**)&f16, g_f);
    cudaGetSymbolAddress((void**)&h16, g_h);
    cudaGetSymbolAddress((void**)&w1h, g_w1t_hi);
    cudaGetSymbolAddress((void**)&w1l, g_w1t_lo);
    cudaGetSymbolAddress((void**)&wch, g_wct_hi);
    cudaGetSymbolAddress((void**)&wcl, g_wct_lo);

    cudaFuncSetAttribute(conv_mma<27, false>, cudaFuncAttributeMaxDynamicSharedMemorySize, SMEM_TOTAL);
    cudaFuncSetAttribute(conv_mma<8,  true >, cudaFuncAttributeMaxDynamicSharedMemorySize, SMEM_TOTAL);

    // prep
    build_wct_kernel<<<dim3(16, 64), 256>>>(W2);
    build_w1t_kernel<<<dim3(16, 27), 256>>>(W1);
    split_feats_kernel<<<((N_VOX + 1) * C / 4 + 255) / 256, 256>>>(feats);

    const int nblk = N_VOX / 64;   // 625
    // layer 1: 27-tap conv -> h (fp16)
    conv_mma<27, false><<<nblk, 256, SMEM_TOTAL>>>(f16, w1h, w1l, nbr1, b1,
                                                   nullptr, h16);
    // layer 2 (collapsed subdivide): 8-tap conv on coarse grid -> out fp32
    conv_mma<8, true><<<dim3(nblk, 8), 256, SMEM_TOTAL>>>(h16, wch, wcl, nbr1, b2,
                                                          out, nullptr);
}

// round 13
// speedup vs baseline: 1.0092x; 1.0092x over previous
#include <cuda_runtime.h>
#include <cuda_fp16.h>
#include <cstdint>

// ============================================================================
// SparseSubdivideBlock3d via legacy HMMA (mma.sync fp16) — one-sided split.
// R12 = R11 resubmitted verbatim (round-12 bench died in broker infra before
// compiling/running; same flake pattern as R2/R3).
// R11: M=128x128 tile (2x MMA work per chunk) + one-sided fp16 split (R10)
//      + mbarrier 2-stage pipeline (R9) + 2 CTAs/SM (stage fits: A16K+B32K).
//   out ~= A*Bhi + A*Blo ; A single fp16, B split hi+lo.
//
// Algorithm (validated R4 @ fp32):
//   conv1: 27-tap submanifold conv, C=128->128, +bias, SiLU
//   subdivide collapse: conv2 == 8-tap conv on the COARSE grid with
//     pre-combined weights Wc[p][e] = sum W2[k], out row = 8*v + p.
// ============================================================================

#define N_VOX 40000
#define C 128

// ---- device scratch ----
__device__ __align__(16) __half g_w1t_hi[27 * C * C];      // W1^T [k][co][ci]
__device__ __align__(16) __half g_w1t_lo[27 * C * C];
__device__ __align__(16) __half g_wct_hi[64 * C * C];      // Wc^T [pe][co][ci]
__device__ __align__(16) __half g_wct_lo[64 * C * C];
__device__ __align__(16) __half g_f[(N_VOX + 1) * C];      // feats fp16 + zero pad row
__device__ __align__(16) __half g_h[(N_VOX + 1) * C];      // layer-1 out fp16 + pad

__device__ __forceinline__ float silu_f(float x) { return x / (1.0f + __expf(-x)); }

__device__ __forceinline__ uint32_t smem_u32(const void* p) {
    uint32_t a;
    asm("{ .reg .u64 t; cvta.to.shared.u64 t, %1; cvt.u32.u64 %0, t; }" : "=r"(a) : "l"(p));
    return a;
}
#define CP16(dst, src) asm volatile("cp.async.cg.shared.global [%0], [%1], 16;" :: "r"(dst), "l"(src))
#define CPA_ARRIVE(mb)  asm volatile("cp.async.mbarrier.arrive.noinc.shared.b64 [%0];" :: "r"((uint32_t)(mb)) : "memory")
#define MBAR_INIT(mb, n) asm volatile("mbarrier.init.shared.b64 [%0], %1;" :: "r"((uint32_t)(mb)), "r"((uint32_t)(n)) : "memory")
#define MBAR_ARRIVE(mb)  asm volatile("mbarrier.arrive.shared.b64 _, [%0];" :: "r"((uint32_t)(mb)) : "memory")

#define MBAR_WAIT(mb, ph) do {                                                             \
    uint32_t _m = (uint32_t)(mb), _p = (uint32_t)(ph), _d;                                 \
    asm volatile("{\n\t.reg .pred p;\n\t"                                                  \
        "mbarrier.try_wait.parity.acquire.cta.shared::cta.b64 p, [%1], %2;\n\t"            \
        "selp.b32 %0, 1, 0, p;\n\t}" : "=r"(_d) : "r"(_m), "r"(_p) : "memory");            \
    if (!_d) {                                                                             \
        asm volatile("{\n\t.reg .pred P1;\n\t"                                             \
            "WL_%=:\n\t"                                                                   \
            "mbarrier.try_wait.parity.acquire.cta.shared::cta.b64 P1, [%0], %1, 0x989680;\n\t" \
            "@P1 bra.uni WD_%=;\n\t"                                                       \
            "bra.uni WL_%=;\n\t"                                                           \
            "WD_%=:\n\t}" :: "r"(_m), "r"(_p) : "memory");                                 \
    }                                                                                      \
} while (0)

__device__ __forceinline__ void ldsm_x4(uint32_t* r, uint32_t a) {
    asm volatile("ldmatrix.sync.aligned.m8n8.x4.shared.b16 {%0,%1,%2,%3}, [%4];"
                 : "=r"(r[0]), "=r"(r[1]), "=r"(r[2]), "=r"(r[3]) : "r"(a));
}
__device__ __forceinline__ void mma16816(float* d, const uint32_t* a, const uint32_t* b) {
    asm volatile("mma.sync.aligned.m16n8k16.row.col.f32.f16.f16.f32 "
                 "{%0,%1,%2,%3}, {%4,%5,%6,%7}, {%8,%9}, {%0,%1,%2,%3};"
                 : "+f"(d[0]), "+f"(d[1]), "+f"(d[2]), "+f"(d[3])
                 : "r"(a[0]), "r"(a[1]), "r"(a[2]), "r"(a[3]), "r"(b[0]), "r"(b[1]));
}

__device__ __forceinline__ void split_h16(float x, __half& hi, __half& lo) {
    hi = __float2half(x);
    lo = __float2half(x - __half2float(hi));
}

// ---------------------------------------------------------------------------
// Prep: fused build + split + transpose (unchanged).
// ---------------------------------------------------------------------------
__global__ void build_wct_kernel(const float* __restrict__ W2) {
    __shared__ float s[32][33];
    const int pe = blockIdx.y;
    const int p = pe >> 3, e = pe & 7;
    const int pp[3] = { (p >> 2) & 1, (p >> 1) & 1, p & 1 };
    const int ee[3] = { (e >> 2) & 1, (e >> 1) & 1, e & 1 };
    int offs[3][2], cnt[3];
    #pragma unroll
    for (int d = 0; d < 3; d++) {
        if (ee[d] == pp[d]) { cnt[d] = 1; offs[d][0] = pp[d] ? 1 : -1; offs[d][1] = 0; }
        else if (pp[d] == 0) { cnt[d] = 2; offs[d][0] = 0;  offs[d][1] = 1; }
        else                 { cnt[d] = 2; offs[d][0] = -1; offs[d][1] = 0; }
    }
    const int ci0 = (blockIdx.x >> 2) * 32, co0 = (blockIdx.x & 3) * 32;
    const int tx = threadIdx.x;
    const int r = tx >> 3, c4 = (tx & 7) * 4;

    float4 sum = make_float4(0.f, 0.f, 0.f, 0.f);
    for (int a = 0; a < cnt[0]; a++)
        for (int b = 0; b < cnt[1]; b++)
            for (int c = 0; c < cnt[2]; c++) {
                int k = (offs[0][a] + 1) * 9 + (offs[1][b] + 1) * 3 + (offs[2][c] + 1);
                float4 v = *(const float4*)(W2 + (size_t)k * (C * C) + (size_t)(ci0 + r) * C + co0 + c4);
                sum.x += v.x; sum.y += v.y; sum.z += v.z; sum.w += v.w;
            }
    s[r][c4] = sum.x; s[r][c4 + 1] = sum.y; s[r][c4 + 2] = sum.z; s[r][c4 + 3] = sum.w;
    __syncthreads();

    __half hi[4], lo[4];
    #pragma unroll
    for (int j = 0; j < 4; ++j) split_h16(s[c4 + j][r], hi[j], lo[j]);
    const size_t o = (size_t)pe * (C * C) + (size_t)(co0 + r) * C + ci0 + c4;
    *(uint2*)(g_wct_hi + o) = *(const uint2*)hi;
    *(uint2*)(g_wct_lo + o) = *(const uint2*)lo;
}

__global__ void build_w1t_kernel(const float* __restrict__ W1) {
    __shared__ float s[32][33];
    const int k = blockIdx.y;
    const int ci0 = (blockIdx.x >> 2) * 32, co0 = (blockIdx.x & 3) * 32;
    const int tx = threadIdx.x;
    const int r = tx >> 3, c4 = (tx & 7) * 4;
    float4 v = *(const float4*)(W1 + (size_t)k * (C * C) + (size_t)(ci0 + r) * C + co0 + c4);
    s[r][c4] = v.x; s[r][c4 + 1] = v.y; s[r][c4 + 2] = v.z; s[r][c4 + 3] = v.w;
    __syncthreads();
    __half hi[4], lo[4];
    #pragma unroll
    for (int j = 0; j < 4; ++j) split_h16(s[c4 + j][r], hi[j], lo[j]);
    const size_t o = (size_t)k * (C * C) + (size_t)(co0 + r) * C + ci0 + c4;
    *(uint2*)(g_w1t_hi + o) = *(const uint2*)hi;
    *(uint2*)(g_w1t_lo + o) = *(const uint2*)lo;
}

__global__ void split_feats_kernel(const float* __restrict__ f) {
    const size_t i4 = ((size_t)blockIdx.x * blockDim.x + threadIdx.x) * 4;
    const size_t tot = (size_t)(N_VOX + 1) * C;
    if (i4 >= tot) return;
    float4 v;
    const bool pad = i4 >= (size_t)N_VOX * C;
    if (pad) v = make_float4(0.f, 0.f, 0.f, 0.f);
    else     v = *(const float4*)(f + i4);
    __half h[4];
    h[0] = __float2half(v.x); h[1] = __float2half(v.y);
    h[2] = __float2half(v.z); h[3] = __float2half(v.w);
    *(uint2*)(g_f + i4) = *(const uint2*)h;
    if (pad) *(uint2*)(g_h + i4) = *(const uint2*)h;   // zeros
}

// ---------------------------------------------------------------------------
// Main conv kernel: 256 threads, block = 128 voxels x 128 outputs, 2 CTAs/SM.
// SMEM: [0,512) bias | [512,14336) sIdx[NOFF][128] | [14336,14368) mbarriers
//       [16384, +2*49152) stage bufs (A 16K | B hi 16K | B lo 16K)
// K chunk = 64, 2-stage mbarrier full/empty pipeline.
// Swizzle: 16B chunk col c at row r stored at chunk (c ^ (r&7)); row = 128B.
// ---------------------------------------------------------------------------
#define MBAR_BASE 14336
#define BUF_OFF 16384
#define STAGE   49152
#define SMEM_TOTAL (BUF_OFF + 2 * STAGE)

template <int NOFF, bool L2>
__global__ __launch_bounds__(256, 2)
void conv_mma(const __half* __restrict__ fin,
              const __half* __restrict__ whi, const __half* __restrict__ wlo,
              const int* __restrict__ nbr, const float* __restrict__ bias,
              float* __restrict__ out, __half* __restrict__ oh) {
    extern __shared__ __align__(1024) char smem[];
    const uint32_t sb = smem_u32(smem);
    const int tx = threadIdx.x, wid = tx >> 5, lane = tx & 31;
    const int m0 = blockIdx.x * 128;
    const int p  = L2 ? blockIdx.y : 0;
    const int p0 = (p >> 2) & 1, p1 = (p >> 1) & 1, p2 = p & 1;
    const int wm = wid & 1;            // 0..1 : 64-row slab
    const int wn = wid >> 1;           // 0..3 : 32-col slab

    float* sBias = (float*)smem;
    int*   sIdx  = (int*)(smem + 512);
    const uint32_t mbFull0  = sb + MBAR_BASE + 0;
    const uint32_t mbFull1  = sb + MBAR_BASE + 8;
    const uint32_t mbEmpty0 = sb + MBAR_BASE + 16;
    const uint32_t mbEmpty1 = sb + MBAR_BASE + 24;

    if (tx == 0) {
        MBAR_INIT(mbFull0, 256);  MBAR_INIT(mbFull1, 256);
        MBAR_INIT(mbEmpty0, 256); MBAR_INIT(mbEmpty1, 256);
    }
    if (tx < C) sBias[tx] = bias[tx];
    for (int t = tx; t < NOFF * 128; t += 256) {
        const int tap = t >> 7, r = t & 127;
        const int col = L2 ? ((((tap >> 2) & 1) + p0) * 9 + (((tap >> 1) & 1) + p1) * 3 + ((tap & 1) + p2))
                           : tap;
        const int row = m0 + r;
        sIdx[t] = (row < N_VOX) ? nbr[(size_t)row * 27 + col] : N_VOX;   // pad -> zero row
    }
    __syncthreads();   // mbarrier init + sIdx visible

    const int NCHUNK = NOFF * 2;

    auto load_chunk = [&](int ch, int buf) {
        const int tap = ch >> 1;
        const int kb  = (ch & 1) * 64;
        const uint32_t base = sb + BUF_OFF + (uint32_t)buf * STAGE;
        const int slice = L2 ? (p * 8 + tap) : tap;
        const __half* wsl_h = whi + (size_t)slice * (C * C);
        const __half* wsl_l = wlo + (size_t)slice * (C * C);
        const int* idx = sIdx + tap * 128;
        #pragma unroll
        for (int i = 0; i < 4; ++i) {                  // A: 1024 16B chunks (fp16 single)
            const int op = tx + i * 256;
            const int row = op >> 3, c = op & 7;
            const int g = idx[row];
            const __half* src = fin + (size_t)g * C + kb + c * 8;
            const uint32_t dst = base + (uint32_t)(row * 128 + ((c ^ (row & 7)) << 4));
            CP16(dst, src);
        }
        #pragma unroll
        for (int i = 0; i < 8; ++i) {                  // B hi+lo: 2048 chunks
            const int op = tx + i * 256;
            const int part = op >> 10;
            const int rc = op & 1023, row = rc >> 3, c = rc & 7;
            const __half* src = (part ? wsl_l : wsl_h) + (size_t)row * C + kb + c * 8;
            const uint32_t dst = base + 16384u + (uint32_t)part * 16384u
                               + (uint32_t)(row * 128 + ((c ^ (row & 7)) << 4));
            CP16(dst, src);
        }
    };

    float acc[4][4][4];
    #pragma unroll
    for (int i = 0; i < 4; i++)
        #pragma unroll
        for (int j = 0; j < 4; j++)
            #pragma unroll
            for (int q = 0; q < 4; q++) acc[i][j][q] = 0.0f;

    // prologue: fill both stages
    load_chunk(0, 0); CPA_ARRIVE(mbFull0);
    load_chunk(1, 1); CPA_ARRIVE(mbFull1);

    #pragma unroll 1
    for (int ch = 0; ch < NCHUNK; ++ch) {
        const int b  = ch & 1;
        const int ph = (ch >> 1) & 1;
        const uint32_t mbF = b ? mbFull1 : mbFull0;
        const uint32_t mbE = b ? mbEmpty1 : mbEmpty0;

        MBAR_WAIT(mbF, ph);                    // loads for chunk ch complete

        const uint32_t base = sb + BUF_OFF + (uint32_t)b * STAGE;
        const uint32_t aB = base, bHi = base + 16384u, bLo = base + 32768u;

        #pragma unroll
        for (int k16 = 0; k16 < 4; ++k16) {
            uint32_t ah[4][4], bh[4][2], bl[4][2];
            #pragma unroll
            for (int i = 0; i < 4; ++i) {
                const int row = wm * 64 + 16 * i + (lane & 15);
                const int c = (k16 << 1) + (lane >> 4);
                const uint32_t off = (uint32_t)(row * 128 + ((c ^ (row & 7)) << 4));
                ldsm_x4(ah[i], aB + off);
            }
            #pragma unroll
            for (int jj = 0; jj < 2; ++jj) {
                const int grp = lane >> 3;
                const int row = wn * 32 + 16 * jj + ((grp >> 1) << 3) + (lane & 7);
                const int c = (k16 << 1) + (grp & 1);
                const uint32_t off = (uint32_t)(row * 128 + ((c ^ (row & 7)) << 4));
                uint32_t t[4];
                ldsm_x4(t, bHi + off);
                bh[jj * 2][0] = t[0]; bh[jj * 2][1] = t[1];
                bh[jj * 2 + 1][0] = t[2]; bh[jj * 2 + 1][1] = t[3];
                ldsm_x4(t, bLo + off);
                bl[jj * 2][0] = t[0]; bl[jj * 2][1] = t[1];
                bl[jj * 2 + 1][0] = t[2]; bl[jj * 2 + 1][1] = t[3];
            }
            #pragma unroll
            for (int i = 0; i < 4; ++i)
                #pragma unroll
                for (int j = 0; j < 4; ++j) {
                    mma16816(acc[i][j], ah[i], bh[j]);
                    mma16816(acc[i][j], ah[i], bl[j]);
                }
        }

        MBAR_ARRIVE(mbE);                      // done reading buffer b
        if (ch + 2 < NCHUNK) {
            MBAR_WAIT(mbE, ph);                // buffer reusable by all threads
            load_chunk(ch + 2, b);
            CPA_ARRIVE(mbF);
        }
    }

    // ---- epilogue: bias + SiLU (guard tail rows) ----
    const int lrow = lane >> 2;             // 0..7
    const int lcol = (lane & 3) * 2;        // 0,2,4,6
    #pragma unroll
    for (int i = 0; i < 4; ++i) {
        const int r0 = m0 + wm * 64 + 16 * i + lrow;
        const int r1 = r0 + 8;
        #pragma unroll
        for (int j = 0; j < 4; ++j) {
            const int cb = wn * 32 + 8 * j + lcol;
            const float b0 = sBias[cb], b1 = sBias[cb + 1];
            float v00 = silu_f(acc[i][j][0] + b0), v01 = silu_f(acc[i][j][1] + b1);
            float v10 = silu_f(acc[i][j][2] + b0), v11 = silu_f(acc[i][j][3] + b1);
            if (L2) {
                if (r0 < N_VOX) *(float2*)(out + ((size_t)r0 * 8 + p) * C + cb) = make_float2(v00, v01);
                if (r1 < N_VOX) *(float2*)(out + ((size_t)r1 * 8 + p) * C + cb) = make_float2(v10, v11);
            } else {
                __half h[2];
                if (r0 < N_VOX) {
                    h[0] = __float2half(v00); h[1] = __float2half(v01);
                    *(uint32_t*)(oh + (size_t)r0 * C + cb) = *(const uint32_t*)h;
                }
                if (r1 < N_VOX) {
                    h[0] = __float2half(v10); h[1] = __float2half(v11);
                    *(uint32_t*)(oh + (size_t)r1 * C + cb) = *(const uint32_t*)h;
                }
            }
        }
    }
}

// ---------------------------------------------------------------------------
// Inputs (metadata order): feats, W1, b1, W2, b2, nbr1, nbr2(unused)
// Output: 320000 x 128 fp32
// ---------------------------------------------------------------------------
extern "C" void kernel_launch(void* const* d_in, const int* in_sizes, int n_in,
                              void* d_out, int out_size) {
    const float* feats = (const float*)d_in[0];
    const float* W1    = (const float*)d_in[1];
    const float* b1    = (const float*)d_in[2];
    const float* W2    = (const float*)d_in[3];
    const float* b2    = (const float*)d_in[4];
    const int*   nbr1  = (const int*)  d_in[5];
    float*       out   = (float*)d_out;

    __half *f16, *h16, *w1h, *w1l, *wch, *wcl;
    cudaGetSymbolAddress((void**)&f16, g_f);
    cudaGetSymbolAddress((void**)&h16, g_h);
    cudaGetSymbolAddress((void**)&w1h, g_w1t_hi);
    cudaGetSymbolAddress((void**)&w1l, g_w1t_lo);
    cudaGetSymbolAddress((void**)&wch, g_wct_hi);
    cudaGetSymbolAddress((void**)&wcl, g_wct_lo);

    cudaFuncSetAttribute(conv_mma<27, false>, cudaFuncAttributeMaxDynamicSharedMemorySize, SMEM_TOTAL);
    cudaFuncSetAttribute(conv_mma<8,  true >, cudaFuncAttributeMaxDynamicSharedMemorySize, SMEM_TOTAL);

    // prep
    build_wct_kernel<<<dim3(16, 64), 256>>>(W2);
    build_w1t_kernel<<<dim3(16, 27), 256>>>(W1);
    split_feats_kernel<<<((N_VOX + 1) * C / 4 + 255) / 256, 256>>>(feats);

    const int nblk = (N_VOX + 127) / 128;   // 313
    // layer 1: 27-tap conv -> h (fp16)
    conv_mma<27, false><<<nblk, 256, SMEM_TOTAL>>>(f16, w1h, w1l, nbr1, b1,
                                                   nullptr, h16);
    // layer 2 (collapsed subdivide): 8-tap conv on coarse grid -> out fp32
    conv_mma<8, true><<<dim3(nblk, 8), 256, SMEM_TOTAL>>>(h16, wch, wcl, nbr1, b2,
                                                          out, nullptr);
}

// round 16
// speedup vs baseline: 1.0709x; 1.0611x over previous
#include <cuda_runtime.h>
#include <cuda_fp16.h>
#include <cstdint>

// ============================================================================
// SparseSubdivideBlock3d via legacy HMMA (mma.sync fp16), plain fp16 operands.
// R16 = R14 resubmitted verbatim AGAIN (rounds 14 and 15 both died in broker
// infra before compiling; R2/R3/R12 showed the same flake clearing on retry).
// R14: (a) drop B-lo split -> 1 MMA per product (error: A-round + B-round in
//      quadrature ~ 4.2e-4, measured one-sided was 2.978e-4);
//      (b) stage shrinks to 24KB -> 3 CTAs/SM (24 warps, 6/scheduler),
//      __launch_bounds__(256,3) caps regs at 85 so ptxas can pipeline frags.
// Geometry = R10: M=64x128 tile, 32x32 warp tile, K-chunk 64, 2-stage
// mbarrier full/empty pipeline.
//
// Algorithm (validated R4 @ fp32):
//   conv1: 27-tap submanifold conv, C=128->128, +bias, SiLU
//   subdivide collapse: conv2 == 8-tap conv on the COARSE grid with
//     pre-combined weights Wc[p][e] = sum W2[k], out row = 8*v + p.
// ============================================================================

#define N_VOX 40000
#define C 128

// ---- device scratch ----
__device__ __align__(16) __half g_w1t[27 * C * C];         // W1^T [k][co][ci] fp16
__device__ __align__(16) __half g_wct[64 * C * C];         // Wc^T [pe][co][ci] fp16
__device__ __align__(16) __half g_f[(N_VOX + 1) * C];      // feats fp16 + zero pad row
__device__ __align__(16) __half g_h[(N_VOX + 1) * C];      // layer-1 out fp16 + pad

__device__ __forceinline__ float silu_f(float x) { return x / (1.0f + __expf(-x)); }

__device__ __forceinline__ uint32_t smem_u32(const void* p) {
    uint32_t a;
    asm("{ .reg .u64 t; cvta.to.shared.u64 t, %1; cvt.u32.u64 %0, t; }" : "=r"(a) : "l"(p));
    return a;
}
#define CP16(dst, src) asm volatile("cp.async.cg.shared.global [%0], [%1], 16;" :: "r"(dst), "l"(src))
#define CPA_ARRIVE(mb)  asm volatile("cp.async.mbarrier.arrive.noinc.shared.b64 [%0];" :: "r"((uint32_t)(mb)) : "memory")
#define MBAR_INIT(mb, n) asm volatile("mbarrier.init.shared.b64 [%0], %1;" :: "r"((uint32_t)(mb)), "r"((uint32_t)(n)) : "memory")
#define MBAR_ARRIVE(mb)  asm volatile("mbarrier.arrive.shared.b64 _, [%0];" :: "r"((uint32_t)(mb)) : "memory")

#define MBAR_WAIT(mb, ph) do {                                                             \
    uint32_t _m = (uint32_t)(mb), _p = (uint32_t)(ph), _d;                                 \
    asm volatile("{\n\t.reg .pred p;\n\t"                                                  \
        "mbarrier.try_wait.parity.acquire.cta.shared::cta.b64 p, [%1], %2;\n\t"            \
        "selp.b32 %0, 1, 0, p;\n\t}" : "=r"(_d) : "r"(_m), "r"(_p) : "memory");            \
    if (!_d) {                                                                             \
        asm volatile("{\n\t.reg .pred P1;\n\t"                                             \
            "WL_%=:\n\t"                                                                   \
            "mbarrier.try_wait.parity.acquire.cta.shared::cta.b64 P1, [%0], %1, 0x989680;\n\t" \
            "@P1 bra.uni WD_%=;\n\t"                                                       \
            "bra.uni WL_%=;\n\t"                                                           \
            "WD_%=:\n\t}" :: "r"(_m), "r"(_p) : "memory");                                 \
    }                                                                                      \
} while (0)

__device__ __forceinline__ void ldsm_x4(uint32_t* r, uint32_t a) {
    asm volatile("ldmatrix.sync.aligned.m8n8.x4.shared.b16 {%0,%1,%2,%3}, [%4];"
                 : "=r"(r[0]), "=r"(r[1]), "=r"(r[2]), "=r"(r[3]) : "r"(a));
}
__device__ __forceinline__ void mma16816(float* d, const uint32_t* a, const uint32_t* b) {
    asm volatile("mma.sync.aligned.m16n8k16.row.col.f32.f16.f16.f32 "
                 "{%0,%1,%2,%3}, {%4,%5,%6,%7}, {%8,%9}, {%0,%1,%2,%3};"
                 : "+f"(d[0]), "+f"(d[1]), "+f"(d[2]), "+f"(d[3])
                 : "r"(a[0]), "r"(a[1]), "r"(a[2]), "r"(a[3]), "r"(b[0]), "r"(b[1]));
}

// ---------------------------------------------------------------------------
// Prep: fused build + transpose -> fp16 (single, round-to-nearest).
// ---------------------------------------------------------------------------
__global__ void build_wct_kernel(const float* __restrict__ W2) {
    __shared__ float s[32][33];
    const int pe = blockIdx.y;
    const int p = pe >> 3, e = pe & 7;
    const int pp[3] = { (p >> 2) & 1, (p >> 1) & 1, p & 1 };
    const int ee[3] = { (e >> 2) & 1, (e >> 1) & 1, e & 1 };
    int offs[3][2], cnt[3];
    #pragma unroll
    for (int d = 0; d < 3; d++) {
        if (ee[d] == pp[d]) { cnt[d] = 1; offs[d][0] = pp[d] ? 1 : -1; offs[d][1] = 0; }
        else if (pp[d] == 0) { cnt[d] = 2; offs[d][0] = 0;  offs[d][1] = 1; }
        else                 { cnt[d] = 2; offs[d][0] = -1; offs[d][1] = 0; }
    }
    const int ci0 = (blockIdx.x >> 2) * 32, co0 = (blockIdx.x & 3) * 32;
    const int tx = threadIdx.x;
    const int r = tx >> 3, c4 = (tx & 7) * 4;

    float4 sum = make_float4(0.f, 0.f, 0.f, 0.f);
    for (int a = 0; a < cnt[0]; a++)
        for (int b = 0; b < cnt[1]; b++)
            for (int c = 0; c < cnt[2]; c++) {
                int k = (offs[0][a] + 1) * 9 + (offs[1][b] + 1) * 3 + (offs[2][c] + 1);
                float4 v = *(const float4*)(W2 + (size_t)k * (C * C) + (size_t)(ci0 + r) * C + co0 + c4);
                sum.x += v.x; sum.y += v.y; sum.z += v.z; sum.w += v.w;
            }
    s[r][c4] = sum.x; s[r][c4 + 1] = sum.y; s[r][c4 + 2] = sum.z; s[r][c4 + 3] = sum.w;
    __syncthreads();

    __half h[4];
    #pragma unroll
    for (int j = 0; j < 4; ++j) h[j] = __float2half(s[c4 + j][r]);
    const size_t o = (size_t)pe * (C * C) + (size_t)(co0 + r) * C + ci0 + c4;
    *(uint2*)(g_wct + o) = *(const uint2*)h;
}

__global__ void build_w1t_kernel(const float* __restrict__ W1) {
    __shared__ float s[32][33];
    const int k = blockIdx.y;
    const int ci0 = (blockIdx.x >> 2) * 32, co0 = (blockIdx.x & 3) * 32;
    const int tx = threadIdx.x;
    const int r = tx >> 3, c4 = (tx & 7) * 4;
    float4 v = *(const float4*)(W1 + (size_t)k * (C * C) + (size_t)(ci0 + r) * C + co0 + c4);
    s[r][c4] = v.x; s[r][c4 + 1] = v.y; s[r][c4 + 2] = v.z; s[r][c4 + 3] = v.w;
    __syncthreads();
    __half h[4];
    #pragma unroll
    for (int j = 0; j < 4; ++j) h[j] = __float2half(s[c4 + j][r]);
    const size_t o = (size_t)k * (C * C) + (size_t)(co0 + r) * C + ci0 + c4;
    *(uint2*)(g_w1t + o) = *(const uint2*)h;
}

__global__ void split_feats_kernel(const float* __restrict__ f) {
    const size_t i4 = ((size_t)blockIdx.x * blockDim.x + threadIdx.x) * 4;
    const size_t tot = (size_t)(N_VOX + 1) * C;
    if (i4 >= tot) return;
    float4 v;
    const bool pad = i4 >= (size_t)N_VOX * C;
    if (pad) v = make_float4(0.f, 0.f, 0.f, 0.f);
    else     v = *(const float4*)(f + i4);
    __half h[4];
    h[0] = __float2half(v.x); h[1] = __float2half(v.y);
    h[2] = __float2half(v.z); h[3] = __float2half(v.w);
    *(uint2*)(g_f + i4) = *(const uint2*)h;
    if (pad) *(uint2*)(g_h + i4) = *(const uint2*)h;   // zeros
}

// ---------------------------------------------------------------------------
// Main conv kernel: 256 threads, block = 64 voxels x 128 outputs, 3 CTAs/SM.
// SMEM: [0,512) bias | [512,7424) sIdx | [7424,7456) mbarriers
//       [8192, +2*24576) stage bufs (A 8K | B 16K)
// K chunk = 64, 2-stage mbarrier full/empty pipeline.
// Swizzle: 16B chunk col c at row r stored at chunk (c ^ (r&7)); row = 128B.
// ---------------------------------------------------------------------------
#define MBAR_BASE 7424
#define BUF_OFF 8192
#define STAGE   24576
#define SMEM_TOTAL (BUF_OFF + 2 * STAGE)

template <int NOFF, bool L2>
__global__ __launch_bounds__(256, 3)
void conv_mma(const __half* __restrict__ fin,
              const __half* __restrict__ w,
              const int* __restrict__ nbr, const float* __restrict__ bias,
              float* __restrict__ out, __half* __restrict__ oh) {
    extern __shared__ __align__(1024) char smem[];
    const uint32_t sb = smem_u32(smem);
    const int tx = threadIdx.x, wid = tx >> 5, lane = tx & 31;
    const int m0 = blockIdx.x * 64;
    const int p  = L2 ? blockIdx.y : 0;
    const int p0 = (p >> 2) & 1, p1 = (p >> 1) & 1, p2 = p & 1;
    const int wm = wid & 1;            // 0..1 : 32-row slab
    const int wn = wid >> 1;           // 0..3 : 32-col slab

    float* sBias = (float*)smem;
    int*   sIdx  = (int*)(smem + 512);
    const uint32_t mbFull0  = sb + MBAR_BASE + 0;
    const uint32_t mbFull1  = sb + MBAR_BASE + 8;
    const uint32_t mbEmpty0 = sb + MBAR_BASE + 16;
    const uint32_t mbEmpty1 = sb + MBAR_BASE + 24;

    if (tx == 0) {
        MBAR_INIT(mbFull0, 256);  MBAR_INIT(mbFull1, 256);
        MBAR_INIT(mbEmpty0, 256); MBAR_INIT(mbEmpty1, 256);
    }
    if (tx < C) sBias[tx] = bias[tx];
    for (int t = tx; t < NOFF * 64; t += 256) {
        const int tap = t >> 6, r = t & 63;
        const int col = L2 ? ((((tap >> 2) & 1) + p0) * 9 + (((tap >> 1) & 1) + p1) * 3 + ((tap & 1) + p2))
                           : tap;
        sIdx[t] = nbr[(size_t)(m0 + r) * 27 + col];   // 625*64 == N_VOX exactly
    }
    __syncthreads();   // mbarrier init + sIdx visible

    const int NCHUNK = NOFF * 2;

    auto load_chunk = [&](int ch, int buf) {
        const int tap = ch >> 1;
        const int kb  = (ch & 1) * 64;
        const uint32_t base = sb + BUF_OFF + (uint32_t)buf * STAGE;
        const int slice = L2 ? (p * 8 + tap) : tap;
        const __half* wsl = w + (size_t)slice * (C * C);
        const int* idx = sIdx + tap * 64;
        #pragma unroll
        for (int i = 0; i < 2; ++i) {                  // A: 512 16B chunks
            const int op = tx + i * 256;
            const int row = op >> 3, c = op & 7;
            const int g = idx[row];
            const __half* src = fin + (size_t)g * C + kb + c * 8;
            const uint32_t dst = base + (uint32_t)(row * 128 + ((c ^ (row & 7)) << 4));
            CP16(dst, src);
        }
        #pragma unroll
        for (int i = 0; i < 4; ++i) {                  // B: 1024 chunks
            const int op = tx + i * 256;
            const int row = op >> 3, c = op & 7;
            const __half* src = wsl + (size_t)row * C + kb + c * 8;
            const uint32_t dst = base + 8192u + (uint32_t)(row * 128 + ((c ^ (row & 7)) << 4));
            CP16(dst, src);
        }
    };

    float acc[2][4][4];
    #pragma unroll
    for (int i = 0; i < 2; i++)
        #pragma unroll
        for (int j = 0; j < 4; j++)
            #pragma unroll
            for (int q = 0; q < 4; q++) acc[i][j][q] = 0.0f;

    // prologue: fill both stages
    load_chunk(0, 0); CPA_ARRIVE(mbFull0);
    load_chunk(1, 1); CPA_ARRIVE(mbFull1);

    #pragma unroll 1
    for (int ch = 0; ch < NCHUNK; ++ch) {
        const int b  = ch & 1;
        const int ph = (ch >> 1) & 1;
        const uint32_t mbF = b ? mbFull1 : mbFull0;
        const uint32_t mbE = b ? mbEmpty1 : mbEmpty0;

        MBAR_WAIT(mbF, ph);                    // loads for chunk ch complete

        const uint32_t base = sb + BUF_OFF + (uint32_t)b * STAGE;
        const uint32_t aB = base, bB = base + 8192u;

        #pragma unroll
        for (int k16 = 0; k16 < 4; ++k16) {
            uint32_t ah[2][4], bf[4][2];
            #pragma unroll
            for (int i = 0; i < 2; ++i) {
                const int row = wm * 32 + 16 * i + (lane & 15);
                const int c = (k16 << 1) + (lane >> 4);
                const uint32_t off = (uint32_t)(row * 128 + ((c ^ (row & 7)) << 4));
                ldsm_x4(ah[i], aB + off);
            }
            #pragma unroll
            for (int jj = 0; jj < 2; ++jj) {
                const int grp = lane >> 3;
                const int row = wn * 32 + 16 * jj + ((grp >> 1) << 3) + (lane & 7);
                const int c = (k16 << 1) + (grp & 1);
                const uint32_t off = (uint32_t)(row * 128 + ((c ^ (row & 7)) << 4));
                uint32_t t[4];
                ldsm_x4(t, bB + off);
                bf[jj * 2][0] = t[0]; bf[jj * 2][1] = t[1];
                bf[jj * 2 + 1][0] = t[2]; bf[jj * 2 + 1][1] = t[3];
            }
            #pragma unroll
            for (int i = 0; i < 2; ++i)
                #pragma unroll
                for (int j = 0; j < 4; ++j)
                    mma16816(acc[i][j], ah[i], bf[j]);
        }

        MBAR_ARRIVE(mbE);                      // done reading buffer b
        if (ch + 2 < NCHUNK) {
            MBAR_WAIT(mbE, ph);                // buffer reusable by all threads
            load_chunk(ch + 2, b);
            CPA_ARRIVE(mbF);
        }
    }

    // ---- epilogue: bias + SiLU ----
    const int lrow = lane >> 2;             // 0..7
    const int lcol = (lane & 3) * 2;        // 0,2,4,6
    #pragma unroll
    for (int i = 0; i < 2; ++i) {
        const int r0 = m0 + wm * 32 + 16 * i + lrow;
        const int r1 = r0 + 8;
        #pragma unroll
        for (int j = 0; j < 4; ++j) {
            const int cb = wn * 32 + 8 * j + lcol;
            const float b0 = sBias[cb], b1 = sBias[cb + 1];
            float v00 = silu_f(acc[i][j][0] + b0), v01 = silu_f(acc[i][j][1] + b1);
            float v10 = silu_f(acc[i][j][2] + b0), v11 = silu_f(acc[i][j][3] + b1);
            if (L2) {
                *(float2*)(out + ((size_t)r0 * 8 + p) * C + cb) = make_float2(v00, v01);
                *(float2*)(out + ((size_t)r1 * 8 + p) * C + cb) = make_float2(v10, v11);
            } else {
                __half h[2];
                h[0] = __float2half(v00); h[1] = __float2half(v01);
                *(uint32_t*)(oh + (size_t)r0 * C + cb) = *(const uint32_t*)h;
                h[0] = __float2half(v10); h[1] = __float2half(v11);
                *(uint32_t*)(oh + (size_t)r1 * C + cb) = *(const uint32_t*)h;
            }
        }
    }
}

// ---------------------------------------------------------------------------
// Inputs (metadata order): feats, W1, b1, W2, b2, nbr1, nbr2(unused)
// Output: 320000 x 128 fp32
// ---------------------------------------------------------------------------
extern "C" void kernel_launch(void* const* d_in, const int* in_sizes, int n_in,
                              void* d_out, int out_size) {
    const float* feats = (const float*)d_in[0];
    const float* W1    = (const float*)d_in[1];
    const float* b1    = (const float*)d_in[2];
    const float* W2    = (const float*)d_in[3];
    const float* b2    = (const float*)d_in[4];
    const int*   nbr1  = (const int*)  d_in[5];
    float*       out   = (float*)d_out;

    __half *f16, *h16, *w1t, *wct;
    cudaGetSymbolAddress((void**)&f16, g_f);
    cudaGetSymbolAddress((void**)&h16, g_h);
    cudaGetSymbolAddress((void**)&w1t, g_w1t);
    cudaGetSymbolAddress((void**)&wct, g_wct);

    cudaFuncSetAttribute(conv_mma<27, false>, cudaFuncAttributeMaxDynamicSharedMemorySize, SMEM_TOTAL);
    cudaFuncSetAttribute(conv_mma<8,  true >, cudaFuncAttributeMaxDynamicSharedMemorySize, SMEM_TOTAL);

    // prep
    build_wct_kernel<<<dim3(16, 64), 256>>>(W2);
    build_w1t_kernel<<<dim3(16, 27), 256>>>(W1);
    split_feats_kernel<<<((N_VOX + 1) * C / 4 + 255) / 256, 256>>>(feats);

    const int nblk = N_VOX / 64;   // 625
    // layer 1: 27-tap conv -> h (fp16)
    conv_mma<27, false><<<nblk, 256, SMEM_TOTAL>>>(f16, w1t, nbr1, b1,
                                                   nullptr, h16);
    // layer 2 (collapsed subdivide): 8-tap conv on coarse grid -> out fp32
    conv_mma<8, true><<<dim3(nblk, 8), 256, SMEM_TOTAL>>>(h16, wct, nbr1, b2,
                                                          out, nullptr);
}